// round 12
// baseline (speedup 1.0000x reference)
#include <cuda_runtime.h>
#include <cuda_bf16.h>
#include <cstdint>
#include <cstddef>

// Problem constants
#define NB 8          // batch
#define NCH 64        // channels == embed dim E
#define NP 4096       // pixels (64x64)
#define NDIM 192      // 3*C
#define NROWS (NB * NP)

// ---------------- device scratch (no allocation allowed) ----------------
__device__ __align__(128) float g_f[(size_t)NB * NDIM * NP];     // conv features [b][192][n]
__device__ __align__(128) float g_q[(size_t)NB * NCH * NP];      // Q [b][e][n]
__device__ __align__(128) float g_k[(size_t)NB * NCH * NP];      // K [b][e][n]
__device__ __align__(128) float g_v[(size_t)NB * NCH * NP];      // V [b][c][n]
__device__ __align__(128) float g_s[(size_t)NB * NP * NP];       // scores -> attn probs [b][q][k]
__device__ __align__(128) float g_impp[(size_t)NB * 8 * NP];     // importance partials
__device__ __align__(128) float g_imp[NROWS];                    // key importance
__device__ __align__(128) float g_mask[NROWS];                   // top-k mask
__device__ __align__(128) float g_numer[(size_t)NB * NP * NCH];  // attn output pre-proj [b][n][c]

// ---------------- tf32 helpers ----------------
__device__ __forceinline__ uint32_t f2tf32(float f) {
    uint32_t r;
    asm("cvt.rna.tf32.f32 %0, %1;" : "=r"(r) : "f"(f));
    return r;
}

__device__ __forceinline__ void mma_tf32(float* c, const uint32_t* a, const uint32_t* b) {
    asm volatile(
        "mma.sync.aligned.m16n8k8.row.col.f32.tf32.tf32.f32 "
        "{%0,%1,%2,%3}, {%4,%5,%6,%7}, {%8,%9}, {%0,%1,%2,%3};\n"
        : "+f"(c[0]), "+f"(c[1]), "+f"(c[2]), "+f"(c[3])
        : "r"(a[0]), "r"(a[1]), "r"(a[2]), "r"(a[3]), "r"(b[0]), "r"(b[1]));
}

// ================= 1. fused multipath conv =================
// grid 512 = (b,h), block 256. writes g_f[b][d][n]
__global__ void __launch_bounds__(256) k_conv(
    const float* __restrict__ x,
    const float* __restrict__ w1, const float* __restrict__ b1,
    const float* __restrict__ w3, const float* __restrict__ b3,
    const float* __restrict__ w5, const float* __restrict__ b5) {
    int b = blockIdx.x >> 6;
    int h = blockIdx.x & 63;
    __shared__ float xs[64][65];  // center row, all channels
    const float* xb = x + (size_t)b * NCH * NP;
    for (int idx = threadIdx.x; idx < 64 * 64; idx += 256) {
        int c = idx >> 6, w = idx & 63;
        xs[c][w] = xb[(size_t)c * NP + h * 64 + w];
    }
    __syncthreads();
    for (int it = 0; it < 16; ++it) {
        int idx = it * 256 + threadIdx.x;
        int c = idx >> 6, w = idx & 63;
        const float* xc = xb + (size_t)c * NP;
        // 1x1 conv over channels
        float a1 = __ldg(b1 + c);
        const float* w1r = w1 + c * 64;
        #pragma unroll 16
        for (int i = 0; i < 64; ++i) a1 = fmaf(xs[i][w], __ldg(w1r + i), a1);
        // 3x3 depthwise, pad 1
        float a2 = __ldg(b3 + c);
        #pragma unroll
        for (int kh = 0; kh < 3; ++kh) {
            int hh = h + kh - 1;
            if ((unsigned)hh < 64u) {
                #pragma unroll
                for (int kw2 = 0; kw2 < 3; ++kw2) {
                    int ww = w + kw2 - 1;
                    if ((unsigned)ww < 64u)
                        a2 = fmaf(__ldg(xc + hh * 64 + ww), __ldg(w3 + c * 9 + kh * 3 + kw2), a2);
                }
            }
        }
        // 5x5 depthwise, pad 2
        float a3 = __ldg(b5 + c);
        #pragma unroll
        for (int kh = 0; kh < 5; ++kh) {
            int hh = h + kh - 2;
            if ((unsigned)hh < 64u) {
                #pragma unroll
                for (int kw2 = 0; kw2 < 5; ++kw2) {
                    int ww = w + kw2 - 2;
                    if ((unsigned)ww < 64u)
                        a3 = fmaf(__ldg(xc + hh * 64 + ww), __ldg(w5 + c * 25 + kh * 5 + kw2), a3);
                }
            }
        }
        int n = h * 64 + w;
        size_t base = (size_t)b * NDIM * NP + n;
        g_f[base + (size_t)c * NP]         = a1;
        g_f[base + (size_t)(64 + c) * NP]  = a2;
        g_f[base + (size_t)(128 + c) * NP] = a3;
    }
}

// ================= 2. QKV projection =================
// grid (32 n-tiles, 8 b), block 256, dyn smem 192*129*4 = 99072 B
__global__ void __launch_bounds__(256) k_qkv(
    const float* __restrict__ qw, const float* __restrict__ qb,
    const float* __restrict__ kw, const float* __restrict__ kb,
    const float* __restrict__ vw, const float* __restrict__ vb) {
    extern __shared__ float fs[];  // [192][129]
    int b = blockIdx.y;
    int n0 = blockIdx.x * 128;
    const float* fb = g_f + (size_t)b * NDIM * NP + n0;
    for (int idx = threadIdx.x; idx < 192 * 128; idx += 256) {
        int d = idx >> 7, nn = idx & 127;
        fs[d * 129 + nn] = fb[(size_t)d * NP + nn];
    }
    __syncthreads();
    int tx = threadIdx.x & 31;   // n lane
    int wid = threadIdx.x >> 5;  // warp 0..7
    const float* Ws[3] = {qw, kw, vw};
    const float* Bs[3] = {qb, kb, vb};
    size_t boff = (size_t)b * NCH * NP;
    float* Os[3] = {g_q + boff, g_k + boff, g_v + boff};

    float acc[3][8][4];
    #pragma unroll
    for (int g = 0; g < 3; ++g)
        #pragma unroll
        for (int i = 0; i < 8; ++i) {
            float bv = __ldg(Bs[g] + wid * 8 + i);
            #pragma unroll
            for (int j = 0; j < 4; ++j) acc[g][i][j] = bv;
        }
    for (int d = 0; d < 192; ++d) {
        float fv0 = fs[d * 129 + tx];
        float fv1 = fs[d * 129 + tx + 32];
        float fv2 = fs[d * 129 + tx + 64];
        float fv3 = fs[d * 129 + tx + 96];
        #pragma unroll
        for (int g = 0; g < 3; ++g)
            #pragma unroll
            for (int i = 0; i < 8; ++i) {
                float wv = __ldg(Ws[g] + (wid * 8 + i) * NDIM + d);  // warp-uniform
                acc[g][i][0] = fmaf(wv, fv0, acc[g][i][0]);
                acc[g][i][1] = fmaf(wv, fv1, acc[g][i][1]);
                acc[g][i][2] = fmaf(wv, fv2, acc[g][i][2]);
                acc[g][i][3] = fmaf(wv, fv3, acc[g][i][3]);
            }
    }
    #pragma unroll
    for (int g = 0; g < 3; ++g)
        #pragma unroll
        for (int i = 0; i < 8; ++i) {
            size_t base = (size_t)(wid * 8 + i) * NP + n0 + tx;
            #pragma unroll
            for (int j = 0; j < 4; ++j) Os[g][base + 32 * j] = acc[g][i][j];
        }
}

// ================= 3. S = Q^T K / 8 via tf32 tensor cores =================
// grid (32 kt, 32 qt, 8 b), block 256 (8 warps), dyn smem 2*64*136*4 = 69632 B
// A = Q^T (q x e), B = K (e x k col-major view). m16n8k8 tiles.
__global__ void __launch_bounds__(256) k_sgemm_tc() {
    extern __shared__ uint32_t sm_u[];
    uint32_t* Qs = sm_u;              // [64][136] tf32
    uint32_t* Ks = sm_u + 64 * 136;   // [64][136] tf32
    int b = blockIdx.z;
    int q0 = blockIdx.y * 128;
    int k0 = blockIdx.x * 128;
    const float* Qb = g_q + (size_t)b * NCH * NP + q0;
    const float* Kb = g_k + (size_t)b * NCH * NP + k0;
    for (int idx = threadIdx.x; idx < 64 * 128; idx += 256) {
        int e = idx >> 7, t = idx & 127;
        Qs[e * 136 + t] = f2tf32(Qb[(size_t)e * NP + t]);
        Ks[e * 136 + t] = f2tf32(Kb[(size_t)e * NP + t]);
    }
    __syncthreads();

    int lane = threadIdx.x & 31, wid = threadIdx.x >> 5;
    int g = lane >> 2, t = lane & 3;
    int wq = (wid & 1) * 64;   // warp q offset (2-way)
    int wk = (wid >> 1) * 32;  // warp k offset (4-way)

    float acc[4][4][4];
    #pragma unroll
    for (int mi = 0; mi < 4; ++mi)
        #pragma unroll
        for (int ni = 0; ni < 4; ++ni)
            #pragma unroll
            for (int r = 0; r < 4; ++r) acc[mi][ni][r] = 0.f;

    #pragma unroll
    for (int e0 = 0; e0 < 64; e0 += 8) {
        uint32_t a[4][4], bf[4][2];
        #pragma unroll
        for (int mi = 0; mi < 4; ++mi) {
            int q = wq + mi * 16 + g;
            a[mi][0] = Qs[(e0 + t) * 136 + q];
            a[mi][1] = Qs[(e0 + t) * 136 + q + 8];
            a[mi][2] = Qs[(e0 + t + 4) * 136 + q];
            a[mi][3] = Qs[(e0 + t + 4) * 136 + q + 8];
        }
        #pragma unroll
        for (int ni = 0; ni < 4; ++ni) {
            int k = wk + ni * 8 + g;
            bf[ni][0] = Ks[(e0 + t) * 136 + k];
            bf[ni][1] = Ks[(e0 + t + 4) * 136 + k];
        }
        #pragma unroll
        for (int mi = 0; mi < 4; ++mi)
            #pragma unroll
            for (int ni = 0; ni < 4; ++ni)
                mma_tf32(acc[mi][ni], a[mi], bf[ni]);
    }

    float* Sb = g_s + ((size_t)b << 24);
    #pragma unroll
    for (int mi = 0; mi < 4; ++mi) {
        #pragma unroll
        for (int ni = 0; ni < 4; ++ni) {
            int q = q0 + wq + mi * 16 + g;
            int k = k0 + wk + ni * 8 + 2 * t;
            float2 v0 = make_float2(acc[mi][ni][0] * 0.125f, acc[mi][ni][1] * 0.125f);
            float2 v1 = make_float2(acc[mi][ni][2] * 0.125f, acc[mi][ni][3] * 0.125f);
            *(float2*)(Sb + (size_t)q * NP + k)       = v0;
            *(float2*)(Sb + (size_t)(q + 8) * NP + k) = v1;
        }
    }
}

// ================= 4. row softmax: overwrite S with p = exp(s-m)/l =================
// grid 32768 (one row per block), block 256
__global__ void __launch_bounds__(256) k_stats() {
    __shared__ float4 buf4[1024];
    __shared__ float red[256];
    size_t row = blockIdx.x;
    float4* S4 = reinterpret_cast<float4*>(g_s + row * NP);
    int tid = threadIdx.x;
    float m = -3.4e38f;
    #pragma unroll
    for (int r = 0; r < 4; ++r) {
        float4 t = S4[tid + 256 * r];
        buf4[tid + 256 * r] = t;
        m = fmaxf(m, fmaxf(fmaxf(t.x, t.y), fmaxf(t.z, t.w)));
    }
    red[tid] = m;
    __syncthreads();
    for (int s = 128; s; s >>= 1) {
        if (tid < s) red[tid] = fmaxf(red[tid], red[tid + s]);
        __syncthreads();
    }
    m = red[0];
    __syncthreads();
    float sum = 0.f;
    #pragma unroll
    for (int r = 0; r < 4; ++r) {
        float4 t = buf4[tid + 256 * r];
        t.x = __expf(t.x - m); t.y = __expf(t.y - m);
        t.z = __expf(t.z - m); t.w = __expf(t.w - m);
        buf4[tid + 256 * r] = t;
        sum += (t.x + t.y) + (t.z + t.w);
    }
    red[tid] = sum;
    __syncthreads();
    for (int s = 128; s; s >>= 1) {
        if (tid < s) red[tid] += red[tid + s];
        __syncthreads();
    }
    float linv = 1.0f / red[0];
    #pragma unroll
    for (int r = 0; r < 4; ++r) {
        float4 t = buf4[tid + 256 * r];
        t.x *= linv; t.y *= linv; t.z *= linv; t.w *= linv;
        S4[tid + 256 * r] = t;
    }
}

// ================= 5. key importance (deterministic split-K column sums) =========
// grid (16 col-tiles, 8 q-chunks, 8 b), block 256
__global__ void __launch_bounds__(256) k_imp() {
    int b = blockIdx.z;
    int col = blockIdx.x * 256 + threadIdx.x;
    int r0 = blockIdx.y * 512;
    const float* Sp = g_s + ((size_t)b << 24) + (size_t)r0 * NP + col;
    float s0 = 0.f, s1 = 0.f, s2 = 0.f, s3 = 0.f;
    for (int r = 0; r < 512; r += 4) {
        s0 += Sp[(size_t)(r + 0) * NP];
        s1 += Sp[(size_t)(r + 1) * NP];
        s2 += Sp[(size_t)(r + 2) * NP];
        s3 += Sp[(size_t)(r + 3) * NP];
    }
    g_impp[((size_t)b * 8 + blockIdx.y) * NP + col] = (s0 + s1) + (s2 + s3);
}

__global__ void k_impred() {
    int idx = blockIdx.x * 256 + threadIdx.x;  // 32768
    int b = idx >> 12, col = idx & 4095;
    float s = 0.f;
    #pragma unroll
    for (int ch = 0; ch < 8; ++ch) s += g_impp[((size_t)b * 8 + ch) * NP + col];
    g_imp[idx] = s;
}

// ================= 6. top-k mask via bitonic sort of (value, index) keys =========
// grid 8 (one block per batch), block 1024, smem 32KB
__global__ void __launch_bounds__(1024) k_topk() {
    __shared__ unsigned long long keys[4096];
    int b = blockIdx.x;
    int tid = threadIdx.x;
    for (int i = tid; i < 4096; i += 1024) {
        unsigned fb = __float_as_uint(g_imp[b * 4096 + i]);  // importance > 0
        keys[i] = ((unsigned long long)fb << 32) | (unsigned)(4095 - i);
    }
    __syncthreads();
    for (int size = 2; size <= 4096; size <<= 1) {
        for (int stride = size >> 1; stride > 0; stride >>= 1) {
            #pragma unroll
            for (int t = 0; t < 2; ++t) {
                int i = t * 1024 + tid;
                int pos = 2 * i - (i & (stride - 1));
                bool desc = ((pos & size) == 0);
                unsigned long long a = keys[pos], c = keys[pos + stride];
                bool sw = desc ? (a < c) : (a > c);
                if (sw) { keys[pos] = c; keys[pos + stride] = a; }
            }
            __syncthreads();
        }
    }
    unsigned long long thresh = keys[2047];  // k_val = 2048
    for (int i = tid; i < 4096; i += 1024) {
        unsigned fb = __float_as_uint(g_imp[b * 4096 + i]);
        unsigned long long key = ((unsigned long long)fb << 32) | (unsigned)(4095 - i);
        g_mask[b * 4096 + i] = (key >= thresh) ? 1.0f : 0.0f;
    }
}

// ================= 7. masked numerator GEMM via tf32 tensor cores =================
// out[q][c] = (sum_k mask*p*V) / (sum_k mask*p + 1e-8)
// grid (32 q-tiles of 128, 8 b), block 256 (8 warps)
// dyn smem: Es[128][68] + Vs[64][68] tf32 = 52224 B
__global__ void __launch_bounds__(256) k_numer_tc() {
    extern __shared__ uint32_t sm_u[];
    uint32_t* Es = sm_u;               // [128][68]  E[q][k] tf32
    uint32_t* Vs = sm_u + 128 * 68;    // [64][68]   V[c][k] tf32 (B col-major: B[k][c]=Vs[c][k])
    __shared__ float ps2[128][2];
    int b = blockIdx.y;
    int q0 = blockIdx.x * 128;
    int tid = threadIdx.x;
    int lane = tid & 31, wid = tid >> 5;
    int g = lane >> 2, t = lane & 3;
    int wq = (wid >> 1) * 32;  // warp q offset (4-way)
    int wc = (wid & 1) * 32;   // warp c offset (2-way)

    const float* Sp = g_s + ((size_t)b << 24) + (size_t)q0 * NP;
    const float* Vb = g_v + (size_t)b * NCH * NP;
    const float* Mb = g_mask + b * NP;

    int lr = tid >> 1;           // row this thread loads (0..127)
    int lh = (tid & 1) * 32;     // col half (0 or 32)
    float rs = 0.f;              // this thread's half-row sum (over all k)

    float acc[2][4][4];
    #pragma unroll
    for (int mi = 0; mi < 2; ++mi)
        #pragma unroll
        for (int ni = 0; ni < 4; ++ni)
            #pragma unroll
            for (int r = 0; r < 4; ++r) acc[mi][ni][r] = 0.f;

    for (int chunk = 0; chunk < 64; ++chunk) {
        int k0 = chunk << 6;
        __syncthreads();  // previous iter's mma done with smem
        // ---- load E chunk [128][64] = p * mask, tf32-rounded; accumulate row sums
        {
            const float4* Sp4 = (const float4*)(Sp + (size_t)lr * NP + k0 + lh);
            const float4* Mp4 = (const float4*)(Mb + k0 + lh);
            uint32_t* Erow = Es + lr * 68 + lh;
            float lsum = 0.f;
            #pragma unroll
            for (int j = 0; j < 8; ++j) {
                float4 s = Sp4[j];
                float4 mk = Mp4[j];
                uint32_t ux = f2tf32(s.x * mk.x);
                uint32_t uy = f2tf32(s.y * mk.y);
                uint32_t uz = f2tf32(s.z * mk.z);
                uint32_t uw = f2tf32(s.w * mk.w);
                lsum += (__uint_as_float(ux) + __uint_as_float(uy)) +
                        (__uint_as_float(uz) + __uint_as_float(uw));
                uint4 u4 = make_uint4(ux, uy, uz, uw);
                *(uint4*)(Erow + 4 * j) = u4;
            }
            rs += lsum;
        }
        // ---- load V chunk [64 c][64 k]
        for (int idx = tid; idx < 64 * 64; idx += 256) {
            int c = idx >> 6, k = idx & 63;
            Vs[c * 68 + k] = f2tf32(Vb[(size_t)c * NP + k0 + k]);
        }
        __syncthreads();
        // ---- mma over the 64-wide k chunk
        #pragma unroll
        for (int kk = 0; kk < 64; kk += 8) {
            uint32_t a[2][4], bf[4][2];
            #pragma unroll
            for (int mi = 0; mi < 2; ++mi) {
                int q = wq + mi * 16 + g;
                a[mi][0] = Es[q * 68 + kk + t];
                a[mi][1] = Es[(q + 8) * 68 + kk + t];
                a[mi][2] = Es[q * 68 + kk + t + 4];
                a[mi][3] = Es[(q + 8) * 68 + kk + t + 4];
            }
            #pragma unroll
            for (int ni = 0; ni < 4; ++ni) {
                int c = wc + ni * 8 + g;
                bf[ni][0] = Vs[c * 68 + kk + t];
                bf[ni][1] = Vs[c * 68 + kk + t + 4];
            }
            #pragma unroll
            for (int mi = 0; mi < 2; ++mi)
                #pragma unroll
                for (int ni = 0; ni < 4; ++ni)
                    mma_tf32(acc[mi][ni], a[mi], bf[ni]);
        }
    }

    // ---- row sums -> smem
    ps2[lr][tid & 1] = rs;
    __syncthreads();

    float* Nb = g_numer + ((size_t)b * NP + q0) * NCH;
    #pragma unroll
    for (int mi = 0; mi < 2; ++mi) {
        int qA = wq + mi * 16 + g;
        int qB = qA + 8;
        float rvA = 1.0f / (ps2[qA][0] + ps2[qA][1] + 1e-8f);
        float rvB = 1.0f / (ps2[qB][0] + ps2[qB][1] + 1e-8f);
        #pragma unroll
        for (int ni = 0; ni < 4; ++ni) {
            int c = wc + ni * 8 + 2 * t;
            float2 v0 = make_float2(acc[mi][ni][0] * rvA, acc[mi][ni][1] * rvA);
            float2 v1 = make_float2(acc[mi][ni][2] * rvB, acc[mi][ni][3] * rvB);
            *(float2*)(Nb + (size_t)qA * NCH + c) = v0;
            *(float2*)(Nb + (size_t)qB * NCH + c) = v1;
        }
    }
}

// ================= 8. output projection + transpose to [b][c][n] =================
// grid (32 n-tiles, 8 b), block 256
__global__ void __launch_bounds__(256) k_out(
    float* __restrict__ out, const float* __restrict__ ow, const float* __restrict__ ob) {
    __shared__ float Ns[128 * 65];
    int b = blockIdx.y;
    int n0 = blockIdx.x * 128;
    int tid = threadIdx.x;
    int tx = tid & 31, wid = tid >> 5;
    const float* Nb = g_numer + ((size_t)b * NP + n0) * NCH;
    for (int idx = tid; idx < 128 * 64; idx += 256) {
        int n = idx >> 6, c = idx & 63;
        Ns[n * 65 + c] = Nb[idx];
    }
    __syncthreads();
    float acc[8][4];
    #pragma unroll
    for (int i = 0; i < 8; ++i) {
        float bv = __ldg(ob + wid * 8 + i);
        #pragma unroll
        for (int j = 0; j < 4; ++j) acc[i][j] = bv;
    }
    for (int c = 0; c < 64; ++c) {
        float f0 = Ns[tx * 65 + c];
        float f1 = Ns[(tx + 32) * 65 + c];
        float f2 = Ns[(tx + 64) * 65 + c];
        float f3 = Ns[(tx + 96) * 65 + c];
        #pragma unroll
        for (int i = 0; i < 8; ++i) {
            float wv = __ldg(ow + (wid * 8 + i) * 64 + c);  // warp-uniform
            acc[i][0] = fmaf(wv, f0, acc[i][0]);
            acc[i][1] = fmaf(wv, f1, acc[i][1]);
            acc[i][2] = fmaf(wv, f2, acc[i][2]);
            acc[i][3] = fmaf(wv, f3, acc[i][3]);
        }
    }
    #pragma unroll
    for (int i = 0; i < 8; ++i) {
        int o = wid * 8 + i;
        float* op = out + ((size_t)b * NCH + o) * NP + n0 + tx;
        op[0]  = acc[i][0];
        op[32] = acc[i][1];
        op[64] = acc[i][2];
        op[96] = acc[i][3];
    }
}

// ================= launch =================
extern "C" void kernel_launch(void* const* d_in, const int* in_sizes, int n_in,
                              void* d_out, int out_size) {
    const float* x  = (const float*)d_in[0];
    const float* w1 = (const float*)d_in[1];
    const float* b1 = (const float*)d_in[2];
    const float* w3 = (const float*)d_in[3];
    const float* b3 = (const float*)d_in[4];
    const float* w5 = (const float*)d_in[5];
    const float* b5 = (const float*)d_in[6];
    const float* qw = (const float*)d_in[7];
    const float* qb = (const float*)d_in[8];
    const float* kw = (const float*)d_in[9];
    const float* kb = (const float*)d_in[10];
    const float* vw = (const float*)d_in[11];
    const float* vb = (const float*)d_in[12];
    const float* ow = (const float*)d_in[13];
    const float* ob = (const float*)d_in[14];
    float* out = (float*)d_out;

    const int QKV_SMEM = 192 * 129 * 4;       // 99072
    const int SG_SMEM  = 2 * 64 * 136 * 4;    // 69632
    const int NU_SMEM  = (128 * 68 + 64 * 68) * 4;  // 52224
    cudaFuncSetAttribute(k_qkv,      cudaFuncAttributeMaxDynamicSharedMemorySize, QKV_SMEM);
    cudaFuncSetAttribute(k_sgemm_tc, cudaFuncAttributeMaxDynamicSharedMemorySize, SG_SMEM);
    cudaFuncSetAttribute(k_numer_tc, cudaFuncAttributeMaxDynamicSharedMemorySize, NU_SMEM);

    k_conv<<<512, 256>>>(x, w1, b1, w3, b3, w5, b5);
    k_qkv<<<dim3(32, 8), 256, QKV_SMEM>>>(qw, qb, kw, kb, vw, vb);
    k_sgemm_tc<<<dim3(32, 32, 8), 256, SG_SMEM>>>();
    k_stats<<<NROWS, 256>>>();
    k_imp<<<dim3(16, 8, 8), 256>>>();
    k_impred<<<128, 256>>>();
    k_topk<<<8, 1024>>>();
    k_numer_tc<<<dim3(32, 8), 256, NU_SMEM>>>();
    k_out<<<dim3(32, 8), 256>>>(out, ow, ob);
}

// round 13
// speedup vs baseline: 1.0017x; 1.0017x over previous
#include <cuda_runtime.h>
#include <cuda_bf16.h>
#include <cstdint>
#include <cstddef>

// Problem constants
#define NB 8          // batch
#define NCH 64        // channels == embed dim E
#define NP 4096       // pixels (64x64)
#define NDIM 192      // 3*C
#define NROWS (NB * NP)

// ---------------- device scratch (no allocation allowed) ----------------
__device__ __align__(128) float g_f[(size_t)NB * NDIM * NP];     // conv features [b][192][n]
__device__ __align__(128) float g_q[(size_t)NB * NCH * NP];      // Q [b][e][n]
__device__ __align__(128) float g_k[(size_t)NB * NCH * NP];      // K [b][e][n]
__device__ __align__(128) float g_v[(size_t)NB * NCH * NP];      // V [b][c][n]
__device__ __align__(128) float g_s[(size_t)NB * NP * NP];       // scores -> attn probs [b][q][k]
__device__ __align__(128) float g_impp[(size_t)NB * 8 * NP];     // importance partials
__device__ __align__(128) float g_imp[NROWS];                    // key importance
__device__ __align__(128) float g_mask[NROWS];                   // top-k mask
__device__ __align__(128) float g_numer[(size_t)NB * NP * NCH];  // attn output pre-proj [b][n][c]

// ---------------- tf32 helpers ----------------
__device__ __forceinline__ uint32_t f2tf32(float f) {
    uint32_t r;
    asm("cvt.rna.tf32.f32 %0, %1;" : "=r"(r) : "f"(f));
    return r;
}

__device__ __forceinline__ void mma_tf32(float* c, const uint32_t* a, const uint32_t* b) {
    asm volatile(
        "mma.sync.aligned.m16n8k8.row.col.f32.tf32.tf32.f32 "
        "{%0,%1,%2,%3}, {%4,%5,%6,%7}, {%8,%9}, {%0,%1,%2,%3};\n"
        : "+f"(c[0]), "+f"(c[1]), "+f"(c[2]), "+f"(c[3])
        : "r"(a[0]), "r"(a[1]), "r"(a[2]), "r"(a[3]), "r"(b[0]), "r"(b[1]));
}

// ================= 1. fused multipath conv =================
// grid 512 = (b,h), block 256. writes g_f[b][d][n]
__global__ void __launch_bounds__(256) k_conv(
    const float* __restrict__ x,
    const float* __restrict__ w1, const float* __restrict__ b1,
    const float* __restrict__ w3, const float* __restrict__ b3,
    const float* __restrict__ w5, const float* __restrict__ b5) {
    int b = blockIdx.x >> 6;
    int h = blockIdx.x & 63;
    __shared__ float xs[64][65];  // center row, all channels
    const float* xb = x + (size_t)b * NCH * NP;
    for (int idx = threadIdx.x; idx < 64 * 64; idx += 256) {
        int c = idx >> 6, w = idx & 63;
        xs[c][w] = xb[(size_t)c * NP + h * 64 + w];
    }
    __syncthreads();
    for (int it = 0; it < 16; ++it) {
        int idx = it * 256 + threadIdx.x;
        int c = idx >> 6, w = idx & 63;
        const float* xc = xb + (size_t)c * NP;
        // 1x1 conv over channels
        float a1 = __ldg(b1 + c);
        const float* w1r = w1 + c * 64;
        #pragma unroll 16
        for (int i = 0; i < 64; ++i) a1 = fmaf(xs[i][w], __ldg(w1r + i), a1);
        // 3x3 depthwise, pad 1
        float a2 = __ldg(b3 + c);
        #pragma unroll
        for (int kh = 0; kh < 3; ++kh) {
            int hh = h + kh - 1;
            if ((unsigned)hh < 64u) {
                #pragma unroll
                for (int kw2 = 0; kw2 < 3; ++kw2) {
                    int ww = w + kw2 - 1;
                    if ((unsigned)ww < 64u)
                        a2 = fmaf(__ldg(xc + hh * 64 + ww), __ldg(w3 + c * 9 + kh * 3 + kw2), a2);
                }
            }
        }
        // 5x5 depthwise, pad 2
        float a3 = __ldg(b5 + c);
        #pragma unroll
        for (int kh = 0; kh < 5; ++kh) {
            int hh = h + kh - 2;
            if ((unsigned)hh < 64u) {
                #pragma unroll
                for (int kw2 = 0; kw2 < 5; ++kw2) {
                    int ww = w + kw2 - 2;
                    if ((unsigned)ww < 64u)
                        a3 = fmaf(__ldg(xc + hh * 64 + ww), __ldg(w5 + c * 25 + kh * 5 + kw2), a3);
                }
            }
        }
        int n = h * 64 + w;
        size_t base = (size_t)b * NDIM * NP + n;
        g_f[base + (size_t)c * NP]         = a1;
        g_f[base + (size_t)(64 + c) * NP]  = a2;
        g_f[base + (size_t)(128 + c) * NP] = a3;
    }
}

// ================= 2. QKV projection =================
// grid (32 n-tiles, 8 b), block 256, dyn smem 192*129*4 = 99072 B
__global__ void __launch_bounds__(256) k_qkv(
    const float* __restrict__ qw, const float* __restrict__ qb,
    const float* __restrict__ kw, const float* __restrict__ kb,
    const float* __restrict__ vw, const float* __restrict__ vb) {
    extern __shared__ float fs[];  // [192][129]
    int b = blockIdx.y;
    int n0 = blockIdx.x * 128;
    const float* fb = g_f + (size_t)b * NDIM * NP + n0;
    for (int idx = threadIdx.x; idx < 192 * 128; idx += 256) {
        int d = idx >> 7, nn = idx & 127;
        fs[d * 129 + nn] = fb[(size_t)d * NP + nn];
    }
    __syncthreads();
    int tx = threadIdx.x & 31;   // n lane
    int wid = threadIdx.x >> 5;  // warp 0..7
    const float* Ws[3] = {qw, kw, vw};
    const float* Bs[3] = {qb, kb, vb};
    size_t boff = (size_t)b * NCH * NP;
    float* Os[3] = {g_q + boff, g_k + boff, g_v + boff};

    float acc[3][8][4];
    #pragma unroll
    for (int g = 0; g < 3; ++g)
        #pragma unroll
        for (int i = 0; i < 8; ++i) {
            float bv = __ldg(Bs[g] + wid * 8 + i);
            #pragma unroll
            for (int j = 0; j < 4; ++j) acc[g][i][j] = bv;
        }
    for (int d = 0; d < 192; ++d) {
        float fv0 = fs[d * 129 + tx];
        float fv1 = fs[d * 129 + tx + 32];
        float fv2 = fs[d * 129 + tx + 64];
        float fv3 = fs[d * 129 + tx + 96];
        #pragma unroll
        for (int g = 0; g < 3; ++g)
            #pragma unroll
            for (int i = 0; i < 8; ++i) {
                float wv = __ldg(Ws[g] + (wid * 8 + i) * NDIM + d);  // warp-uniform
                acc[g][i][0] = fmaf(wv, fv0, acc[g][i][0]);
                acc[g][i][1] = fmaf(wv, fv1, acc[g][i][1]);
                acc[g][i][2] = fmaf(wv, fv2, acc[g][i][2]);
                acc[g][i][3] = fmaf(wv, fv3, acc[g][i][3]);
            }
    }
    #pragma unroll
    for (int g = 0; g < 3; ++g)
        #pragma unroll
        for (int i = 0; i < 8; ++i) {
            size_t base = (size_t)(wid * 8 + i) * NP + n0 + tx;
            #pragma unroll
            for (int j = 0; j < 4; ++j) Os[g][base + 32 * j] = acc[g][i][j];
        }
}

// ================= 3. S = Q^T K / 8 via tf32 tensor cores =================
// grid (32 kt, 32 qt, 8 b), block 256 (8 warps), dyn smem 2*64*136*4 = 69632 B
// A = Q^T (q x e), B = K (e x k col-major view). m16n8k8 tiles.
__global__ void __launch_bounds__(256) k_sgemm_tc() {
    extern __shared__ uint32_t sm_u[];
    uint32_t* Qs = sm_u;              // [64][136] tf32
    uint32_t* Ks = sm_u + 64 * 136;   // [64][136] tf32
    int b = blockIdx.z;
    int q0 = blockIdx.y * 128;
    int k0 = blockIdx.x * 128;
    const float* Qb = g_q + (size_t)b * NCH * NP + q0;
    const float* Kb = g_k + (size_t)b * NCH * NP + k0;
    for (int idx = threadIdx.x; idx < 64 * 128; idx += 256) {
        int e = idx >> 7, t = idx & 127;
        Qs[e * 136 + t] = f2tf32(Qb[(size_t)e * NP + t]);
        Ks[e * 136 + t] = f2tf32(Kb[(size_t)e * NP + t]);
    }
    __syncthreads();

    int lane = threadIdx.x & 31, wid = threadIdx.x >> 5;
    int g = lane >> 2, t = lane & 3;
    int wq = (wid & 1) * 64;   // warp q offset (2-way)
    int wk = (wid >> 1) * 32;  // warp k offset (4-way)

    float acc[4][4][4];
    #pragma unroll
    for (int mi = 0; mi < 4; ++mi)
        #pragma unroll
        for (int ni = 0; ni < 4; ++ni)
            #pragma unroll
            for (int r = 0; r < 4; ++r) acc[mi][ni][r] = 0.f;

    #pragma unroll
    for (int e0 = 0; e0 < 64; e0 += 8) {
        uint32_t a[4][4], bf[4][2];
        #pragma unroll
        for (int mi = 0; mi < 4; ++mi) {
            int q = wq + mi * 16 + g;
            a[mi][0] = Qs[(e0 + t) * 136 + q];
            a[mi][1] = Qs[(e0 + t) * 136 + q + 8];
            a[mi][2] = Qs[(e0 + t + 4) * 136 + q];
            a[mi][3] = Qs[(e0 + t + 4) * 136 + q + 8];
        }
        #pragma unroll
        for (int ni = 0; ni < 4; ++ni) {
            int k = wk + ni * 8 + g;
            bf[ni][0] = Ks[(e0 + t) * 136 + k];
            bf[ni][1] = Ks[(e0 + t + 4) * 136 + k];
        }
        #pragma unroll
        for (int mi = 0; mi < 4; ++mi)
            #pragma unroll
            for (int ni = 0; ni < 4; ++ni)
                mma_tf32(acc[mi][ni], a[mi], bf[ni]);
    }

    float* Sb = g_s + ((size_t)b << 24);
    #pragma unroll
    for (int mi = 0; mi < 4; ++mi) {
        #pragma unroll
        for (int ni = 0; ni < 4; ++ni) {
            int q = q0 + wq + mi * 16 + g;
            int k = k0 + wk + ni * 8 + 2 * t;
            float2 v0 = make_float2(acc[mi][ni][0] * 0.125f, acc[mi][ni][1] * 0.125f);
            float2 v1 = make_float2(acc[mi][ni][2] * 0.125f, acc[mi][ni][3] * 0.125f);
            *(float2*)(Sb + (size_t)q * NP + k)       = v0;
            *(float2*)(Sb + (size_t)(q + 8) * NP + k) = v1;
        }
    }
}

// ================= 4. row softmax: overwrite S with p = exp(s-m)/l =================
// grid 32768 (one row per block), block 256
__global__ void __launch_bounds__(256) k_stats() {
    __shared__ float4 buf4[1024];
    __shared__ float red[256];
    size_t row = blockIdx.x;
    float4* S4 = reinterpret_cast<float4*>(g_s + row * NP);
    int tid = threadIdx.x;
    float m = -3.4e38f;
    #pragma unroll
    for (int r = 0; r < 4; ++r) {
        float4 t = S4[tid + 256 * r];
        buf4[tid + 256 * r] = t;
        m = fmaxf(m, fmaxf(fmaxf(t.x, t.y), fmaxf(t.z, t.w)));
    }
    red[tid] = m;
    __syncthreads();
    for (int s = 128; s; s >>= 1) {
        if (tid < s) red[tid] = fmaxf(red[tid], red[tid + s]);
        __syncthreads();
    }
    m = red[0];
    __syncthreads();
    float sum = 0.f;
    #pragma unroll
    for (int r = 0; r < 4; ++r) {
        float4 t = buf4[tid + 256 * r];
        t.x = __expf(t.x - m); t.y = __expf(t.y - m);
        t.z = __expf(t.z - m); t.w = __expf(t.w - m);
        buf4[tid + 256 * r] = t;
        sum += (t.x + t.y) + (t.z + t.w);
    }
    red[tid] = sum;
    __syncthreads();
    for (int s = 128; s; s >>= 1) {
        if (tid < s) red[tid] += red[tid + s];
        __syncthreads();
    }
    float linv = 1.0f / red[0];
    #pragma unroll
    for (int r = 0; r < 4; ++r) {
        float4 t = buf4[tid + 256 * r];
        t.x *= linv; t.y *= linv; t.z *= linv; t.w *= linv;
        S4[tid + 256 * r] = t;
    }
}

// ================= 5. key importance (deterministic split-K column sums) =========
// grid (16 col-tiles, 8 q-chunks, 8 b), block 256
__global__ void __launch_bounds__(256) k_imp() {
    int b = blockIdx.z;
    int col = blockIdx.x * 256 + threadIdx.x;
    int r0 = blockIdx.y * 512;
    const float* Sp = g_s + ((size_t)b << 24) + (size_t)r0 * NP + col;
    float s0 = 0.f, s1 = 0.f, s2 = 0.f, s3 = 0.f;
    for (int r = 0; r < 512; r += 4) {
        s0 += Sp[(size_t)(r + 0) * NP];
        s1 += Sp[(size_t)(r + 1) * NP];
        s2 += Sp[(size_t)(r + 2) * NP];
        s3 += Sp[(size_t)(r + 3) * NP];
    }
    g_impp[((size_t)b * 8 + blockIdx.y) * NP + col] = (s0 + s1) + (s2 + s3);
}

__global__ void k_impred() {
    int idx = blockIdx.x * 256 + threadIdx.x;  // 32768
    int b = idx >> 12, col = idx & 4095;
    float s = 0.f;
    #pragma unroll
    for (int ch = 0; ch < 8; ++ch) s += g_impp[((size_t)b * 8 + ch) * NP + col];
    g_imp[idx] = s;
}

// ================= 6. top-k mask via bitonic sort of (value, index) keys =========
// grid 8 (one block per batch), block 1024, smem 32KB
__global__ void __launch_bounds__(1024) k_topk() {
    __shared__ unsigned long long keys[4096];
    int b = blockIdx.x;
    int tid = threadIdx.x;
    for (int i = tid; i < 4096; i += 1024) {
        unsigned fb = __float_as_uint(g_imp[b * 4096 + i]);  // importance > 0
        keys[i] = ((unsigned long long)fb << 32) | (unsigned)(4095 - i);
    }
    __syncthreads();
    for (int size = 2; size <= 4096; size <<= 1) {
        for (int stride = size >> 1; stride > 0; stride >>= 1) {
            #pragma unroll
            for (int t = 0; t < 2; ++t) {
                int i = t * 1024 + tid;
                int pos = 2 * i - (i & (stride - 1));
                bool desc = ((pos & size) == 0);
                unsigned long long a = keys[pos], c = keys[pos + stride];
                bool sw = desc ? (a < c) : (a > c);
                if (sw) { keys[pos] = c; keys[pos + stride] = a; }
            }
            __syncthreads();
        }
    }
    unsigned long long thresh = keys[2047];  // k_val = 2048
    for (int i = tid; i < 4096; i += 1024) {
        unsigned fb = __float_as_uint(g_imp[b * 4096 + i]);
        unsigned long long key = ((unsigned long long)fb << 32) | (unsigned)(4095 - i);
        g_mask[b * 4096 + i] = (key >= thresh) ? 1.0f : 0.0f;
    }
}

// ================= 7. masked numerator GEMM via tf32 tensor cores =================
// out[q][c] = (sum_k mask*p*V) / (sum_k mask*p + 1e-8)
// grid (32 q-tiles of 128, 8 b), block 256 (8 warps)
// dyn smem: Es[128][68] + Vs[64][68] tf32 = 52224 B
__global__ void __launch_bounds__(256) k_numer_tc() {
    extern __shared__ uint32_t sm_u[];
    uint32_t* Es = sm_u;               // [128][68]  E[q][k] tf32
    uint32_t* Vs = sm_u + 128 * 68;    // [64][68]   V[c][k] tf32 (B col-major: B[k][c]=Vs[c][k])
    __shared__ float ps2[128][2];
    int b = blockIdx.y;
    int q0 = blockIdx.x * 128;
    int tid = threadIdx.x;
    int lane = tid & 31, wid = tid >> 5;
    int g = lane >> 2, t = lane & 3;
    int wq = (wid >> 1) * 32;  // warp q offset (4-way)
    int wc = (wid & 1) * 32;   // warp c offset (2-way)

    const float* Sp = g_s + ((size_t)b << 24) + (size_t)q0 * NP;
    const float* Vb = g_v + (size_t)b * NCH * NP;
    const float* Mb = g_mask + b * NP;

    int lr = tid >> 1;           // row this thread loads (0..127)
    int lh = (tid & 1) * 32;     // col half (0 or 32)
    float rs = 0.f;              // this thread's half-row sum (over all k)

    float acc[2][4][4];
    #pragma unroll
    for (int mi = 0; mi < 2; ++mi)
        #pragma unroll
        for (int ni = 0; ni < 4; ++ni)
            #pragma unroll
            for (int r = 0; r < 4; ++r) acc[mi][ni][r] = 0.f;

    for (int chunk = 0; chunk < 64; ++chunk) {
        int k0 = chunk << 6;
        __syncthreads();  // previous iter's mma done with smem
        // ---- load E chunk [128][64] = p * mask, tf32-rounded; accumulate row sums
        {
            const float4* Sp4 = (const float4*)(Sp + (size_t)lr * NP + k0 + lh);
            const float4* Mp4 = (const float4*)(Mb + k0 + lh);
            uint32_t* Erow = Es + lr * 68 + lh;
            float lsum = 0.f;
            #pragma unroll
            for (int j = 0; j < 8; ++j) {
                float4 s = Sp4[j];
                float4 mk = Mp4[j];
                uint32_t ux = f2tf32(s.x * mk.x);
                uint32_t uy = f2tf32(s.y * mk.y);
                uint32_t uz = f2tf32(s.z * mk.z);
                uint32_t uw = f2tf32(s.w * mk.w);
                lsum += (__uint_as_float(ux) + __uint_as_float(uy)) +
                        (__uint_as_float(uz) + __uint_as_float(uw));
                uint4 u4 = make_uint4(ux, uy, uz, uw);
                *(uint4*)(Erow + 4 * j) = u4;
            }
            rs += lsum;
        }
        // ---- load V chunk [64 c][64 k]
        for (int idx = tid; idx < 64 * 64; idx += 256) {
            int c = idx >> 6, k = idx & 63;
            Vs[c * 68 + k] = f2tf32(Vb[(size_t)c * NP + k0 + k]);
        }
        __syncthreads();
        // ---- mma over the 64-wide k chunk
        #pragma unroll
        for (int kk = 0; kk < 64; kk += 8) {
            uint32_t a[2][4], bf[4][2];
            #pragma unroll
            for (int mi = 0; mi < 2; ++mi) {
                int q = wq + mi * 16 + g;
                a[mi][0] = Es[q * 68 + kk + t];
                a[mi][1] = Es[(q + 8) * 68 + kk + t];
                a[mi][2] = Es[q * 68 + kk + t + 4];
                a[mi][3] = Es[(q + 8) * 68 + kk + t + 4];
            }
            #pragma unroll
            for (int ni = 0; ni < 4; ++ni) {
                int c = wc + ni * 8 + g;
                bf[ni][0] = Vs[c * 68 + kk + t];
                bf[ni][1] = Vs[c * 68 + kk + t + 4];
            }
            #pragma unroll
            for (int mi = 0; mi < 2; ++mi)
                #pragma unroll
                for (int ni = 0; ni < 4; ++ni)
                    mma_tf32(acc[mi][ni], a[mi], bf[ni]);
        }
    }

    // ---- row sums -> smem
    ps2[lr][tid & 1] = rs;
    __syncthreads();

    float* Nb = g_numer + ((size_t)b * NP + q0) * NCH;
    #pragma unroll
    for (int mi = 0; mi < 2; ++mi) {
        int qA = wq + mi * 16 + g;
        int qB = qA + 8;
        float rvA = 1.0f / (ps2[qA][0] + ps2[qA][1] + 1e-8f);
        float rvB = 1.0f / (ps2[qB][0] + ps2[qB][1] + 1e-8f);
        #pragma unroll
        for (int ni = 0; ni < 4; ++ni) {
            int c = wc + ni * 8 + 2 * t;
            float2 v0 = make_float2(acc[mi][ni][0] * rvA, acc[mi][ni][1] * rvA);
            float2 v1 = make_float2(acc[mi][ni][2] * rvB, acc[mi][ni][3] * rvB);
            *(float2*)(Nb + (size_t)qA * NCH + c) = v0;
            *(float2*)(Nb + (size_t)qB * NCH + c) = v1;
        }
    }
}

// ================= 8. output projection + transpose to [b][c][n] =================
// grid (32 n-tiles, 8 b), block 256
__global__ void __launch_bounds__(256) k_out(
    float* __restrict__ out, const float* __restrict__ ow, const float* __restrict__ ob) {
    __shared__ float Ns[128 * 65];
    int b = blockIdx.y;
    int n0 = blockIdx.x * 128;
    int tid = threadIdx.x;
    int tx = tid & 31, wid = tid >> 5;
    const float* Nb = g_numer + ((size_t)b * NP + n0) * NCH;
    for (int idx = tid; idx < 128 * 64; idx += 256) {
        int n = idx >> 6, c = idx & 63;
        Ns[n * 65 + c] = Nb[idx];
    }
    __syncthreads();
    float acc[8][4];
    #pragma unroll
    for (int i = 0; i < 8; ++i) {
        float bv = __ldg(ob + wid * 8 + i);
        #pragma unroll
        for (int j = 0; j < 4; ++j) acc[i][j] = bv;
    }
    for (int c = 0; c < 64; ++c) {
        float f0 = Ns[tx * 65 + c];
        float f1 = Ns[(tx + 32) * 65 + c];
        float f2 = Ns[(tx + 64) * 65 + c];
        float f3 = Ns[(tx + 96) * 65 + c];
        #pragma unroll
        for (int i = 0; i < 8; ++i) {
            float wv = __ldg(ow + (wid * 8 + i) * 64 + c);  // warp-uniform
            acc[i][0] = fmaf(wv, f0, acc[i][0]);
            acc[i][1] = fmaf(wv, f1, acc[i][1]);
            acc[i][2] = fmaf(wv, f2, acc[i][2]);
            acc[i][3] = fmaf(wv, f3, acc[i][3]);
        }
    }
    #pragma unroll
    for (int i = 0; i < 8; ++i) {
        int o = wid * 8 + i;
        float* op = out + ((size_t)b * NCH + o) * NP + n0 + tx;
        op[0]  = acc[i][0];
        op[32] = acc[i][1];
        op[64] = acc[i][2];
        op[96] = acc[i][3];
    }
}

// ================= launch =================
extern "C" void kernel_launch(void* const* d_in, const int* in_sizes, int n_in,
                              void* d_out, int out_size) {
    const float* x  = (const float*)d_in[0];
    const float* w1 = (const float*)d_in[1];
    const float* b1 = (const float*)d_in[2];
    const float* w3 = (const float*)d_in[3];
    const float* b3 = (const float*)d_in[4];
    const float* w5 = (const float*)d_in[5];
    const float* b5 = (const float*)d_in[6];
    const float* qw = (const float*)d_in[7];
    const float* qb = (const float*)d_in[8];
    const float* kw = (const float*)d_in[9];
    const float* kb = (const float*)d_in[10];
    const float* vw = (const float*)d_in[11];
    const float* vb = (const float*)d_in[12];
    const float* ow = (const float*)d_in[13];
    const float* ob = (const float*)d_in[14];
    float* out = (float*)d_out;

    const int QKV_SMEM = 192 * 129 * 4;       // 99072
    const int SG_SMEM  = 2 * 64 * 136 * 4;    // 69632
    const int NU_SMEM  = (128 * 68 + 64 * 68) * 4;  // 52224
    cudaFuncSetAttribute(k_qkv,      cudaFuncAttributeMaxDynamicSharedMemorySize, QKV_SMEM);
    cudaFuncSetAttribute(k_sgemm_tc, cudaFuncAttributeMaxDynamicSharedMemorySize, SG_SMEM);
    cudaFuncSetAttribute(k_numer_tc, cudaFuncAttributeMaxDynamicSharedMemorySize, NU_SMEM);

    k_conv<<<512, 256>>>(x, w1, b1, w3, b3, w5, b5);
    k_qkv<<<dim3(32, 8), 256, QKV_SMEM>>>(qw, qb, kw, kb, vw, vb);
    k_sgemm_tc<<<dim3(32, 32, 8), 256, SG_SMEM>>>();
    k_stats<<<NROWS, 256>>>();
    k_imp<<<dim3(16, 8, 8), 256>>>();
    k_impred<<<128, 256>>>();
    k_topk<<<8, 1024>>>();
    k_numer_tc<<<dim3(32, 8), 256, NU_SMEM>>>();
    k_out<<<dim3(32, 8), 256>>>(out, ow, ob);
}

// round 14
// speedup vs baseline: 1.0097x; 1.0080x over previous
#include <cuda_runtime.h>
#include <cuda_bf16.h>
#include <cstdint>
#include <cstddef>

// Problem constants
#define NB 8          // batch
#define NCH 64        // channels == embed dim E
#define NP 4096       // pixels (64x64)
#define NDIM 192      // 3*C
#define NROWS (NB * NP)

// ---------------- device scratch (no allocation allowed) ----------------
__device__ __align__(128) float g_f[(size_t)NB * NDIM * NP];     // conv features [b][192][n]
__device__ __align__(128) float g_q[(size_t)NB * NCH * NP];      // Q [b][e][n]
__device__ __align__(128) float g_k[(size_t)NB * NCH * NP];      // K [b][e][n]
__device__ __align__(128) float g_v[(size_t)NB * NCH * NP];      // V [b][c][n]
__device__ __align__(128) float g_s[(size_t)NB * NP * NP];       // scores -> attn probs [b][q][k]
__device__ __align__(128) float g_impp[(size_t)NB * 8 * NP];     // importance partials
__device__ __align__(128) float g_imp[NROWS];                    // key importance
__device__ __align__(128) float g_mask[NROWS];                   // top-k mask
__device__ __align__(128) float g_numer[(size_t)NB * NP * NCH];  // attn output pre-proj [b][n][c]

// ---------------- tf32 helpers ----------------
__device__ __forceinline__ uint32_t f2tf32(float f) {
    uint32_t r;
    asm("cvt.rna.tf32.f32 %0, %1;" : "=r"(r) : "f"(f));
    return r;
}

__device__ __forceinline__ void mma_tf32(float* c, const uint32_t* a, const uint32_t* b) {
    asm volatile(
        "mma.sync.aligned.m16n8k8.row.col.f32.tf32.tf32.f32 "
        "{%0,%1,%2,%3}, {%4,%5,%6,%7}, {%8,%9}, {%0,%1,%2,%3};\n"
        : "+f"(c[0]), "+f"(c[1]), "+f"(c[2]), "+f"(c[3])
        : "r"(a[0]), "r"(a[1]), "r"(a[2]), "r"(a[3]), "r"(b[0]), "r"(b[1]));
}

// ================= 1. fused multipath conv =================
// grid 512 = (b,h), block 256. writes g_f[b][d][n]
__global__ void __launch_bounds__(256) k_conv(
    const float* __restrict__ x,
    const float* __restrict__ w1, const float* __restrict__ b1,
    const float* __restrict__ w3, const float* __restrict__ b3,
    const float* __restrict__ w5, const float* __restrict__ b5) {
    int b = blockIdx.x >> 6;
    int h = blockIdx.x & 63;
    __shared__ float xs[64][65];  // center row, all channels
    const float* xb = x + (size_t)b * NCH * NP;
    for (int idx = threadIdx.x; idx < 64 * 64; idx += 256) {
        int c = idx >> 6, w = idx & 63;
        xs[c][w] = xb[(size_t)c * NP + h * 64 + w];
    }
    __syncthreads();
    for (int it = 0; it < 16; ++it) {
        int idx = it * 256 + threadIdx.x;
        int c = idx >> 6, w = idx & 63;
        const float* xc = xb + (size_t)c * NP;
        // 1x1 conv over channels
        float a1 = __ldg(b1 + c);
        const float* w1r = w1 + c * 64;
        #pragma unroll 16
        for (int i = 0; i < 64; ++i) a1 = fmaf(xs[i][w], __ldg(w1r + i), a1);
        // 3x3 depthwise, pad 1
        float a2 = __ldg(b3 + c);
        #pragma unroll
        for (int kh = 0; kh < 3; ++kh) {
            int hh = h + kh - 1;
            if ((unsigned)hh < 64u) {
                #pragma unroll
                for (int kw2 = 0; kw2 < 3; ++kw2) {
                    int ww = w + kw2 - 1;
                    if ((unsigned)ww < 64u)
                        a2 = fmaf(__ldg(xc + hh * 64 + ww), __ldg(w3 + c * 9 + kh * 3 + kw2), a2);
                }
            }
        }
        // 5x5 depthwise, pad 2
        float a3 = __ldg(b5 + c);
        #pragma unroll
        for (int kh = 0; kh < 5; ++kh) {
            int hh = h + kh - 2;
            if ((unsigned)hh < 64u) {
                #pragma unroll
                for (int kw2 = 0; kw2 < 5; ++kw2) {
                    int ww = w + kw2 - 2;
                    if ((unsigned)ww < 64u)
                        a3 = fmaf(__ldg(xc + hh * 64 + ww), __ldg(w5 + c * 25 + kh * 5 + kw2), a3);
                }
            }
        }
        int n = h * 64 + w;
        size_t base = (size_t)b * NDIM * NP + n;
        g_f[base + (size_t)c * NP]         = a1;
        g_f[base + (size_t)(64 + c) * NP]  = a2;
        g_f[base + (size_t)(128 + c) * NP] = a3;
    }
}

// ================= 2. QKV projection =================
// grid (32 n-tiles, 8 b), block 256, dyn smem 192*129*4 = 99072 B
__global__ void __launch_bounds__(256) k_qkv(
    const float* __restrict__ qw, const float* __restrict__ qb,
    const float* __restrict__ kw, const float* __restrict__ kb,
    const float* __restrict__ vw, const float* __restrict__ vb) {
    extern __shared__ float fs[];  // [192][129]
    int b = blockIdx.y;
    int n0 = blockIdx.x * 128;
    const float* fb = g_f + (size_t)b * NDIM * NP + n0;
    for (int idx = threadIdx.x; idx < 192 * 128; idx += 256) {
        int d = idx >> 7, nn = idx & 127;
        fs[d * 129 + nn] = fb[(size_t)d * NP + nn];
    }
    __syncthreads();
    int tx = threadIdx.x & 31;   // n lane
    int wid = threadIdx.x >> 5;  // warp 0..7
    const float* Ws[3] = {qw, kw, vw};
    const float* Bs[3] = {qb, kb, vb};
    size_t boff = (size_t)b * NCH * NP;
    float* Os[3] = {g_q + boff, g_k + boff, g_v + boff};

    float acc[3][8][4];
    #pragma unroll
    for (int g = 0; g < 3; ++g)
        #pragma unroll
        for (int i = 0; i < 8; ++i) {
            float bv = __ldg(Bs[g] + wid * 8 + i);
            #pragma unroll
            for (int j = 0; j < 4; ++j) acc[g][i][j] = bv;
        }
    for (int d = 0; d < 192; ++d) {
        float fv0 = fs[d * 129 + tx];
        float fv1 = fs[d * 129 + tx + 32];
        float fv2 = fs[d * 129 + tx + 64];
        float fv3 = fs[d * 129 + tx + 96];
        #pragma unroll
        for (int g = 0; g < 3; ++g)
            #pragma unroll
            for (int i = 0; i < 8; ++i) {
                float wv = __ldg(Ws[g] + (wid * 8 + i) * NDIM + d);  // warp-uniform
                acc[g][i][0] = fmaf(wv, fv0, acc[g][i][0]);
                acc[g][i][1] = fmaf(wv, fv1, acc[g][i][1]);
                acc[g][i][2] = fmaf(wv, fv2, acc[g][i][2]);
                acc[g][i][3] = fmaf(wv, fv3, acc[g][i][3]);
            }
    }
    #pragma unroll
    for (int g = 0; g < 3; ++g)
        #pragma unroll
        for (int i = 0; i < 8; ++i) {
            size_t base = (size_t)(wid * 8 + i) * NP + n0 + tx;
            #pragma unroll
            for (int j = 0; j < 4; ++j) Os[g][base + 32 * j] = acc[g][i][j];
        }
}

// ================= 3. S = Q^T K / 8 via tf32 tensor cores =================
// grid (32 kt, 32 qt, 8 b), block 256 (8 warps), dyn smem 2*64*136*4 = 69632 B
// A = Q^T (q x e), B = K (e x k col-major view). m16n8k8 tiles.
__global__ void __launch_bounds__(256) k_sgemm_tc() {
    extern __shared__ uint32_t sm_u[];
    uint32_t* Qs = sm_u;              // [64][136] tf32
    uint32_t* Ks = sm_u + 64 * 136;   // [64][136] tf32
    int b = blockIdx.z;
    int q0 = blockIdx.y * 128;
    int k0 = blockIdx.x * 128;
    const float* Qb = g_q + (size_t)b * NCH * NP + q0;
    const float* Kb = g_k + (size_t)b * NCH * NP + k0;
    for (int idx = threadIdx.x; idx < 64 * 128; idx += 256) {
        int e = idx >> 7, t = idx & 127;
        Qs[e * 136 + t] = f2tf32(Qb[(size_t)e * NP + t]);
        Ks[e * 136 + t] = f2tf32(Kb[(size_t)e * NP + t]);
    }
    __syncthreads();

    int lane = threadIdx.x & 31, wid = threadIdx.x >> 5;
    int g = lane >> 2, t = lane & 3;
    int wq = (wid & 1) * 64;   // warp q offset (2-way)
    int wk = (wid >> 1) * 32;  // warp k offset (4-way)

    float acc[4][4][4];
    #pragma unroll
    for (int mi = 0; mi < 4; ++mi)
        #pragma unroll
        for (int ni = 0; ni < 4; ++ni)
            #pragma unroll
            for (int r = 0; r < 4; ++r) acc[mi][ni][r] = 0.f;

    #pragma unroll
    for (int e0 = 0; e0 < 64; e0 += 8) {
        uint32_t a[4][4], bf[4][2];
        #pragma unroll
        for (int mi = 0; mi < 4; ++mi) {
            int q = wq + mi * 16 + g;
            a[mi][0] = Qs[(e0 + t) * 136 + q];
            a[mi][1] = Qs[(e0 + t) * 136 + q + 8];
            a[mi][2] = Qs[(e0 + t + 4) * 136 + q];
            a[mi][3] = Qs[(e0 + t + 4) * 136 + q + 8];
        }
        #pragma unroll
        for (int ni = 0; ni < 4; ++ni) {
            int k = wk + ni * 8 + g;
            bf[ni][0] = Ks[(e0 + t) * 136 + k];
            bf[ni][1] = Ks[(e0 + t + 4) * 136 + k];
        }
        #pragma unroll
        for (int mi = 0; mi < 4; ++mi)
            #pragma unroll
            for (int ni = 0; ni < 4; ++ni)
                mma_tf32(acc[mi][ni], a[mi], bf[ni]);
    }

    float* Sb = g_s + ((size_t)b << 24);
    #pragma unroll
    for (int mi = 0; mi < 4; ++mi) {
        #pragma unroll
        for (int ni = 0; ni < 4; ++ni) {
            int q = q0 + wq + mi * 16 + g;
            int k = k0 + wk + ni * 8 + 2 * t;
            float2 v0 = make_float2(acc[mi][ni][0] * 0.125f, acc[mi][ni][1] * 0.125f);
            float2 v1 = make_float2(acc[mi][ni][2] * 0.125f, acc[mi][ni][3] * 0.125f);
            *(float2*)(Sb + (size_t)q * NP + k)       = v0;
            *(float2*)(Sb + (size_t)(q + 8) * NP + k) = v1;
        }
    }
}

// ================= 4. row softmax: overwrite S with p = exp(s-m)/l =================
// grid 32768 (one row per block), block 256
__global__ void __launch_bounds__(256) k_stats() {
    __shared__ float4 buf4[1024];
    __shared__ float red[256];
    size_t row = blockIdx.x;
    float4* S4 = reinterpret_cast<float4*>(g_s + row * NP);
    int tid = threadIdx.x;
    float m = -3.4e38f;
    #pragma unroll
    for (int r = 0; r < 4; ++r) {
        float4 t = S4[tid + 256 * r];
        buf4[tid + 256 * r] = t;
        m = fmaxf(m, fmaxf(fmaxf(t.x, t.y), fmaxf(t.z, t.w)));
    }
    red[tid] = m;
    __syncthreads();
    for (int s = 128; s; s >>= 1) {
        if (tid < s) red[tid] = fmaxf(red[tid], red[tid + s]);
        __syncthreads();
    }
    m = red[0];
    __syncthreads();
    float sum = 0.f;
    #pragma unroll
    for (int r = 0; r < 4; ++r) {
        float4 t = buf4[tid + 256 * r];
        t.x = __expf(t.x - m); t.y = __expf(t.y - m);
        t.z = __expf(t.z - m); t.w = __expf(t.w - m);
        buf4[tid + 256 * r] = t;
        sum += (t.x + t.y) + (t.z + t.w);
    }
    red[tid] = sum;
    __syncthreads();
    for (int s = 128; s; s >>= 1) {
        if (tid < s) red[tid] += red[tid + s];
        __syncthreads();
    }
    float linv = 1.0f / red[0];
    #pragma unroll
    for (int r = 0; r < 4; ++r) {
        float4 t = buf4[tid + 256 * r];
        t.x *= linv; t.y *= linv; t.z *= linv; t.w *= linv;
        S4[tid + 256 * r] = t;
    }
}

// ================= 5. key importance (deterministic split-K column sums) =========
// grid (16 col-tiles, 8 q-chunks, 8 b), block 256
__global__ void __launch_bounds__(256) k_imp() {
    int b = blockIdx.z;
    int col = blockIdx.x * 256 + threadIdx.x;
    int r0 = blockIdx.y * 512;
    const float* Sp = g_s + ((size_t)b << 24) + (size_t)r0 * NP + col;
    float s0 = 0.f, s1 = 0.f, s2 = 0.f, s3 = 0.f;
    for (int r = 0; r < 512; r += 4) {
        s0 += Sp[(size_t)(r + 0) * NP];
        s1 += Sp[(size_t)(r + 1) * NP];
        s2 += Sp[(size_t)(r + 2) * NP];
        s3 += Sp[(size_t)(r + 3) * NP];
    }
    g_impp[((size_t)b * 8 + blockIdx.y) * NP + col] = (s0 + s1) + (s2 + s3);
}

__global__ void k_impred() {
    int idx = blockIdx.x * 256 + threadIdx.x;  // 32768
    int b = idx >> 12, col = idx & 4095;
    float s = 0.f;
    #pragma unroll
    for (int ch = 0; ch < 8; ++ch) s += g_impp[((size_t)b * 8 + ch) * NP + col];
    g_imp[idx] = s;
}

// ================= 6. top-k mask via bitonic sort of (value, index) keys =========
// grid 8 (one block per batch), block 1024, smem 32KB
__global__ void __launch_bounds__(1024) k_topk() {
    __shared__ unsigned long long keys[4096];
    int b = blockIdx.x;
    int tid = threadIdx.x;
    for (int i = tid; i < 4096; i += 1024) {
        unsigned fb = __float_as_uint(g_imp[b * 4096 + i]);  // importance > 0
        keys[i] = ((unsigned long long)fb << 32) | (unsigned)(4095 - i);
    }
    __syncthreads();
    for (int size = 2; size <= 4096; size <<= 1) {
        for (int stride = size >> 1; stride > 0; stride >>= 1) {
            #pragma unroll
            for (int t = 0; t < 2; ++t) {
                int i = t * 1024 + tid;
                int pos = 2 * i - (i & (stride - 1));
                bool desc = ((pos & size) == 0);
                unsigned long long a = keys[pos], c = keys[pos + stride];
                bool sw = desc ? (a < c) : (a > c);
                if (sw) { keys[pos] = c; keys[pos + stride] = a; }
            }
            __syncthreads();
        }
    }
    unsigned long long thresh = keys[2047];  // k_val = 2048
    for (int i = tid; i < 4096; i += 1024) {
        unsigned fb = __float_as_uint(g_imp[b * 4096 + i]);
        unsigned long long key = ((unsigned long long)fb << 32) | (unsigned)(4095 - i);
        g_mask[b * 4096 + i] = (key >= thresh) ? 1.0f : 0.0f;
    }
}

// ================= 7. masked numerator GEMM via tf32 tensor cores =================
// out[q][c] = (sum_k mask*p*V) / (sum_k mask*p + 1e-8)
// grid (32 q-tiles of 128, 8 b), block 256 (8 warps)
// dyn smem: Es[128][68] + Vs[64][68] tf32 = 52224 B
__global__ void __launch_bounds__(256) k_numer_tc() {
    extern __shared__ uint32_t sm_u[];
    uint32_t* Es = sm_u;               // [128][68]  E[q][k] tf32
    uint32_t* Vs = sm_u + 128 * 68;    // [64][68]   V[c][k] tf32 (B col-major: B[k][c]=Vs[c][k])
    __shared__ float ps2[128][2];
    int b = blockIdx.y;
    int q0 = blockIdx.x * 128;
    int tid = threadIdx.x;
    int lane = tid & 31, wid = tid >> 5;
    int g = lane >> 2, t = lane & 3;
    int wq = (wid >> 1) * 32;  // warp q offset (4-way)
    int wc = (wid & 1) * 32;   // warp c offset (2-way)

    const float* Sp = g_s + ((size_t)b << 24) + (size_t)q0 * NP;
    const float* Vb = g_v + (size_t)b * NCH * NP;
    const float* Mb = g_mask + b * NP;

    int lr = tid >> 1;           // row this thread loads (0..127)
    int lh = (tid & 1) * 32;     // col half (0 or 32)
    float rs = 0.f;              // this thread's half-row sum (over all k)

    float acc[2][4][4];
    #pragma unroll
    for (int mi = 0; mi < 2; ++mi)
        #pragma unroll
        for (int ni = 0; ni < 4; ++ni)
            #pragma unroll
            for (int r = 0; r < 4; ++r) acc[mi][ni][r] = 0.f;

    for (int chunk = 0; chunk < 64; ++chunk) {
        int k0 = chunk << 6;
        __syncthreads();  // previous iter's mma done with smem
        // ---- load E chunk [128][64] = p * mask, tf32-rounded; accumulate row sums
        {
            const float4* Sp4 = (const float4*)(Sp + (size_t)lr * NP + k0 + lh);
            const float4* Mp4 = (const float4*)(Mb + k0 + lh);
            uint32_t* Erow = Es + lr * 68 + lh;
            float lsum = 0.f;
            #pragma unroll
            for (int j = 0; j < 8; ++j) {
                float4 s = Sp4[j];
                float4 mk = Mp4[j];
                uint32_t ux = f2tf32(s.x * mk.x);
                uint32_t uy = f2tf32(s.y * mk.y);
                uint32_t uz = f2tf32(s.z * mk.z);
                uint32_t uw = f2tf32(s.w * mk.w);
                lsum += (__uint_as_float(ux) + __uint_as_float(uy)) +
                        (__uint_as_float(uz) + __uint_as_float(uw));
                uint4 u4 = make_uint4(ux, uy, uz, uw);
                *(uint4*)(Erow + 4 * j) = u4;
            }
            rs += lsum;
        }
        // ---- load V chunk [64 c][64 k]
        for (int idx = tid; idx < 64 * 64; idx += 256) {
            int c = idx >> 6, k = idx & 63;
            Vs[c * 68 + k] = f2tf32(Vb[(size_t)c * NP + k0 + k]);
        }
        __syncthreads();
        // ---- mma over the 64-wide k chunk
        #pragma unroll
        for (int kk = 0; kk < 64; kk += 8) {
            uint32_t a[2][4], bf[4][2];
            #pragma unroll
            for (int mi = 0; mi < 2; ++mi) {
                int q = wq + mi * 16 + g;
                a[mi][0] = Es[q * 68 + kk + t];
                a[mi][1] = Es[(q + 8) * 68 + kk + t];
                a[mi][2] = Es[q * 68 + kk + t + 4];
                a[mi][3] = Es[(q + 8) * 68 + kk + t + 4];
            }
            #pragma unroll
            for (int ni = 0; ni < 4; ++ni) {
                int c = wc + ni * 8 + g;
                bf[ni][0] = Vs[c * 68 + kk + t];
                bf[ni][1] = Vs[c * 68 + kk + t + 4];
            }
            #pragma unroll
            for (int mi = 0; mi < 2; ++mi)
                #pragma unroll
                for (int ni = 0; ni < 4; ++ni)
                    mma_tf32(acc[mi][ni], a[mi], bf[ni]);
        }
    }

    // ---- row sums -> smem
    ps2[lr][tid & 1] = rs;
    __syncthreads();

    float* Nb = g_numer + ((size_t)b * NP + q0) * NCH;
    #pragma unroll
    for (int mi = 0; mi < 2; ++mi) {
        int qA = wq + mi * 16 + g;
        int qB = qA + 8;
        float rvA = 1.0f / (ps2[qA][0] + ps2[qA][1] + 1e-8f);
        float rvB = 1.0f / (ps2[qB][0] + ps2[qB][1] + 1e-8f);
        #pragma unroll
        for (int ni = 0; ni < 4; ++ni) {
            int c = wc + ni * 8 + 2 * t;
            float2 v0 = make_float2(acc[mi][ni][0] * rvA, acc[mi][ni][1] * rvA);
            float2 v1 = make_float2(acc[mi][ni][2] * rvB, acc[mi][ni][3] * rvB);
            *(float2*)(Nb + (size_t)qA * NCH + c) = v0;
            *(float2*)(Nb + (size_t)qB * NCH + c) = v1;
        }
    }
}

// ================= 8. output projection + transpose to [b][c][n] =================
// grid (32 n-tiles, 8 b), block 256
__global__ void __launch_bounds__(256) k_out(
    float* __restrict__ out, const float* __restrict__ ow, const float* __restrict__ ob) {
    __shared__ float Ns[128 * 65];
    int b = blockIdx.y;
    int n0 = blockIdx.x * 128;
    int tid = threadIdx.x;
    int tx = tid & 31, wid = tid >> 5;
    const float* Nb = g_numer + ((size_t)b * NP + n0) * NCH;
    for (int idx = tid; idx < 128 * 64; idx += 256) {
        int n = idx >> 6, c = idx & 63;
        Ns[n * 65 + c] = Nb[idx];
    }
    __syncthreads();
    float acc[8][4];
    #pragma unroll
    for (int i = 0; i < 8; ++i) {
        float bv = __ldg(ob + wid * 8 + i);
        #pragma unroll
        for (int j = 0; j < 4; ++j) acc[i][j] = bv;
    }
    for (int c = 0; c < 64; ++c) {
        float f0 = Ns[tx * 65 + c];
        float f1 = Ns[(tx + 32) * 65 + c];
        float f2 = Ns[(tx + 64) * 65 + c];
        float f3 = Ns[(tx + 96) * 65 + c];
        #pragma unroll
        for (int i = 0; i < 8; ++i) {
            float wv = __ldg(ow + (wid * 8 + i) * 64 + c);  // warp-uniform
            acc[i][0] = fmaf(wv, f0, acc[i][0]);
            acc[i][1] = fmaf(wv, f1, acc[i][1]);
            acc[i][2] = fmaf(wv, f2, acc[i][2]);
            acc[i][3] = fmaf(wv, f3, acc[i][3]);
        }
    }
    #pragma unroll
    for (int i = 0; i < 8; ++i) {
        int o = wid * 8 + i;
        float* op = out + ((size_t)b * NCH + o) * NP + n0 + tx;
        op[0]  = acc[i][0];
        op[32] = acc[i][1];
        op[64] = acc[i][2];
        op[96] = acc[i][3];
    }
}

// ================= launch =================
extern "C" void kernel_launch(void* const* d_in, const int* in_sizes, int n_in,
                              void* d_out, int out_size) {
    const float* x  = (const float*)d_in[0];
    const float* w1 = (const float*)d_in[1];
    const float* b1 = (const float*)d_in[2];
    const float* w3 = (const float*)d_in[3];
    const float* b3 = (const float*)d_in[4];
    const float* w5 = (const float*)d_in[5];
    const float* b5 = (const float*)d_in[6];
    const float* qw = (const float*)d_in[7];
    const float* qb = (const float*)d_in[8];
    const float* kw = (const float*)d_in[9];
    const float* kb = (const float*)d_in[10];
    const float* vw = (const float*)d_in[11];
    const float* vb = (const float*)d_in[12];
    const float* ow = (const float*)d_in[13];
    const float* ob = (const float*)d_in[14];
    float* out = (float*)d_out;

    const int QKV_SMEM = 192 * 129 * 4;       // 99072
    const int SG_SMEM  = 2 * 64 * 136 * 4;    // 69632
    const int NU_SMEM  = (128 * 68 + 64 * 68) * 4;  // 52224
    cudaFuncSetAttribute(k_qkv,      cudaFuncAttributeMaxDynamicSharedMemorySize, QKV_SMEM);
    cudaFuncSetAttribute(k_sgemm_tc, cudaFuncAttributeMaxDynamicSharedMemorySize, SG_SMEM);
    cudaFuncSetAttribute(k_numer_tc, cudaFuncAttributeMaxDynamicSharedMemorySize, NU_SMEM);

    k_conv<<<512, 256>>>(x, w1, b1, w3, b3, w5, b5);
    k_qkv<<<dim3(32, 8), 256, QKV_SMEM>>>(qw, qb, kw, kb, vw, vb);
    k_sgemm_tc<<<dim3(32, 32, 8), 256, SG_SMEM>>>();
    k_stats<<<NROWS, 256>>>();
    k_imp<<<dim3(16, 8, 8), 256>>>();
    k_impred<<<128, 256>>>();
    k_topk<<<8, 1024>>>();
    k_numer_tc<<<dim3(32, 8), 256, NU_SMEM>>>();
    k_out<<<dim3(32, 8), 256>>>(out, ow, ob);
}